// round 5
// baseline (speedup 1.0000x reference)
#include <cuda_runtime.h>
#include <math.h>

// Problem constants
#define BT   16          // B*T
#define E    768
#define NXD  32
#define NYD  32
#define NP   1024        // NX*NY
#define TOK  (BT*NP)     // 16384 tokens
#define KM   12          // kept y modes
#define J24  24          // kept x modes (kx = 5..28)
#define KX0  5
#define NMODE 288        // 24*12
#define HID  3072
#define TWO_PI_32 0.19634954084936207f

// ---------------- scratch (static device allocations; no cudaMalloc) ----------------
__device__ float g_h [TOK*E];          // LN1 output
__device__ float g_U [BT*NXD*KM*E];    // fwd y-DFT real
__device__ float g_V [BT*NXD*KM*E];    // fwd y-DFT imag
__device__ float g_fr[BT*NMODE*E];
__device__ float g_fi[BT*NMODE*E];
__device__ float g_sr[BT*NMODE*E];
__device__ float g_si[BT*NMODE*E];
__device__ float g_P [BT*NXD*KM*E];    // inv x-iDFT real (pre-weighted)
__device__ float g_Q [BT*NXD*KM*E];
__device__ float g_r1[TOK*E];          // spat + h + input  (res2)
__device__ float g_y [TOK*E];          // LN2 output
__device__ float g_mid[(size_t)TOK*HID]; // gelu(y@mw1+mb1)

__device__ __forceinline__ float gelu_f(float x) {
    return 0.5f * x * (1.0f + erff(x * 0.7071067811865475f));
}
__device__ __forceinline__ float softshrink_f(float x) {
    return x > 0.01f ? x - 0.01f : (x < -0.01f ? x + 0.01f : 0.0f);
}

// ---------------- LayerNorm (one block per token, 256 threads, 3 elems/thread) ----------------
__device__ __forceinline__ void ln_row(const float* __restrict__ xr,
                                       const float* __restrict__ g,
                                       const float* __restrict__ b,
                                       float* __restrict__ orow) {
    int t = threadIdx.x;
    float v0 = xr[t], v1 = xr[t + 256], v2 = xr[t + 512];
    float s  = v0 + v1 + v2;
    float s2 = v0*v0 + v1*v1 + v2*v2;
    #pragma unroll
    for (int o = 16; o > 0; o >>= 1) {
        s  += __shfl_down_sync(0xffffffffu, s,  o);
        s2 += __shfl_down_sync(0xffffffffu, s2, o);
    }
    __shared__ float sa[8], sb[8];
    __shared__ float mS, rS;
    if ((t & 31) == 0) { sa[t >> 5] = s; sb[t >> 5] = s2; }
    __syncthreads();
    if (t == 0) {
        float ts = 0.f, ts2 = 0.f;
        #pragma unroll
        for (int i = 0; i < 8; i++) { ts += sa[i]; ts2 += sb[i]; }
        float m = ts * (1.0f / 768.0f);
        float var = ts2 * (1.0f / 768.0f) - m * m;
        mS = m; rS = rsqrtf(var + 1e-5f);
    }
    __syncthreads();
    float m = mS, r = rS;
    orow[t]       = (v0 - m) * r * g[t]       + b[t];
    orow[t + 256] = (v1 - m) * r * g[t + 256] + b[t + 256];
    orow[t + 512] = (v2 - m) * r * g[t + 512] + b[t + 512];
}

__global__ void ln1_kernel(const float* __restrict__ x,
                           const float* __restrict__ g,
                           const float* __restrict__ b) {
    size_t row = blockIdx.x;
    ln_row(x + row * E, g, b, g_h + row * E);
}
__global__ void ln2_kernel(const float* __restrict__ g,
                           const float* __restrict__ b) {
    size_t row = blockIdx.x;
    ln_row(g_r1 + row * E, g, b, g_y + row * E);
}

// ---------------- forward DFT stage 1 (over y): U+iV = sum_y h * e^{-2pi i ky y/32} ----------------
// grid: BT*NX blocks, 768 threads (e)
__global__ void fwd_y_kernel() {
    __shared__ float C[32], S[32];
    if (threadIdx.x < 32) {
        float a = threadIdx.x * TWO_PI_32;
        C[threadIdx.x] = cosf(a); S[threadIdx.x] = sinf(a);
    }
    __syncthreads();
    int e = threadIdx.x;
    int bx = blockIdx.x;                    // bt*32 + x
    float U[KM], V[KM];
    #pragma unroll
    for (int k = 0; k < KM; k++) { U[k] = 0.f; V[k] = 0.f; }
    const float* hp = g_h + (size_t)bx * 32 * E + e;
    for (int y = 0; y < 32; y++) {
        float v = hp[(size_t)y * E];
        #pragma unroll
        for (int ky = 0; ky < KM; ky++) {
            int m = (y * ky) & 31;
            U[ky] += v * C[m];
            V[ky] -= v * S[m];
        }
    }
    float* up = g_U + (size_t)bx * KM * E + e;
    float* vp = g_V + (size_t)bx * KM * E + e;
    #pragma unroll
    for (int ky = 0; ky < KM; ky++) {
        up[(size_t)ky * E] = U[ky];
        vp[(size_t)ky * E] = V[ky];
    }
}

// ---------------- forward DFT stage 2 (over x): fr+i*fi = (1/32) sum_x (U+iV) e^{-2pi i kx x/32} ----------------
// grid: (BT*KM, 2) blocks, 768 threads; blockIdx.y picks half of the 24 kx modes
__global__ void fwd_x_kernel() {
    __shared__ float C[32], S[32];
    if (threadIdx.x < 32) {
        float a = threadIdx.x * TWO_PI_32;
        C[threadIdx.x] = cosf(a); S[threadIdx.x] = sinf(a);
    }
    __syncthreads();
    int e  = threadIdx.x;
    int ky = blockIdx.x % KM;
    int bt = blockIdx.x / KM;
    int j0 = blockIdx.y * 12;
    float fr[12], fi[12];
    #pragma unroll
    for (int j = 0; j < 12; j++) { fr[j] = 0.f; fi[j] = 0.f; }
    const float* up = g_U + ((size_t)(bt * 32) * KM + ky) * E + e;
    const float* vp = g_V + ((size_t)(bt * 32) * KM + ky) * E + e;
    for (int x = 0; x < 32; x++) {
        float u = up[(size_t)x * KM * E];
        float v = vp[(size_t)x * KM * E];
        #pragma unroll
        for (int jj = 0; jj < 12; jj++) {
            int kx = j0 + jj + KX0;
            int m = (kx * x) & 31;
            float c = C[m], s = S[m];
            fr[jj] += u * c + v * s;
            fi[jj] += v * c - u * s;
        }
    }
    const float sc = 1.0f / 32.0f;
    #pragma unroll
    for (int jj = 0; jj < 12; jj++) {
        size_t idx = ((size_t)bt * NMODE + (size_t)(j0 + jj) * KM + ky) * E + e;
        g_fr[idx] = fr[jj] * sc;
        g_fi[idx] = fi[jj] * sc;
    }
}

// ---------------- block-diagonal complex MLP (per mode position) ----------------
// grid: BT*NMODE blocks, 768 threads (one output channel per thread)
__global__ void bmlp_kernel(const float* __restrict__ w1, const float* __restrict__ b1,
                            const float* __restrict__ w2, const float* __restrict__ b2) {
    __shared__ float sfr[768], sfi[768], sar[768], sai[768];
    int t = threadIdx.x;
    size_t base = (size_t)blockIdx.x * E;
    sfr[t] = g_fr[base + t];
    sfi[t] = g_fi[base + t];
    __syncthreads();
    int n = t >> 6, oi = t & 63;

    // layer 1:  o1 = gelu( (fr + i fi) @ (w1[0] + i w1[1]) + (b1[0] + i b1[1]) )
    const float* w0p = w1 + ((size_t)n * 64) * 64 + oi;
    const float* w1p = w1 + ((size_t)(12 + n) * 64) * 64 + oi;
    const float* frb = sfr + n * 64;
    const float* fib = sfi + n * 64;
    float ar = b1[t];
    float ai = b1[768 + t];
    #pragma unroll 8
    for (int i = 0; i < 64; i++) {
        float a = w0p[(size_t)i * 64];
        float bb = w1p[(size_t)i * 64];
        float fr = frb[i], fi = fib[i];
        ar += fr * a - fi * bb;
        ai += fi * a + fr * bb;
    }
    sar[t] = gelu_f(ar);
    sai[t] = gelu_f(ai);
    __syncthreads();

    // layer 2 + softshrink
    const float* u0p = w2 + ((size_t)n * 64) * 64 + oi;
    const float* u1p = w2 + ((size_t)(12 + n) * 64) * 64 + oi;
    const float* orb = sar + n * 64;
    const float* oib = sai + n * 64;
    float cr = b2[t];
    float ci = b2[768 + t];
    #pragma unroll 8
    for (int i = 0; i < 64; i++) {
        float a = u0p[(size_t)i * 64];
        float bb = u1p[(size_t)i * 64];
        float orr = orb[i], oii = oib[i];
        cr += orr * a - oii * bb;
        ci += oii * a + orr * bb;
    }
    g_sr[base + t] = softshrink_f(cr);
    g_si[base + t] = softshrink_f(ci);
}

// ---------------- inverse stage 1 (over kx): P+iQ = w(ky)/32 * sum_j (sr+i si) e^{+2pi i kx x/32} ----------------
// grid: BT*NX*KM blocks, 768 threads
__global__ void inv_x_kernel() {
    __shared__ float C[32], S[32];
    if (threadIdx.x < 32) {
        float a = threadIdx.x * TWO_PI_32;
        C[threadIdx.x] = cosf(a); S[threadIdx.x] = sinf(a);
    }
    __syncthreads();
    int e  = threadIdx.x;
    int bx = blockIdx.x;
    int ky = bx % KM;
    int x  = (bx / KM) % 32;
    int bt = bx / (32 * KM);
    float P = 0.f, Q = 0.f;
    const float* srp = g_sr + ((size_t)bt * NMODE + ky) * E + e;
    const float* sip = g_si + ((size_t)bt * NMODE + ky) * E + e;
    #pragma unroll 4
    for (int j = 0; j < J24; j++) {
        float sr = srp[(size_t)j * KM * E];
        float si = sip[(size_t)j * KM * E];
        int m = ((j + KX0) * x) & 31;
        float c = C[m], s = S[m];
        P += sr * c - si * s;
        Q += sr * s + si * c;
    }
    float wgt = (ky == 0 ? 1.0f : 2.0f) * (1.0f / 32.0f);   // Hermitian doubling for ky>=1
    size_t idx = ((size_t)(bt * 32 + x) * KM + ky) * E + e;
    g_P[idx] = P * wgt;
    g_Q[idx] = Q * wgt;
}

// ---------------- inverse stage 2 (over ky) + residual adds: out1 = spat + h + input ----------------
// grid: BT*NX blocks, 768 threads
__global__ void inv_y_kernel(const float* __restrict__ inp) {
    __shared__ float C[32], S[32];
    if (threadIdx.x < 32) {
        float a = threadIdx.x * TWO_PI_32;
        C[threadIdx.x] = cosf(a); S[threadIdx.x] = sinf(a);
    }
    __syncthreads();
    int e = threadIdx.x;
    int bx = blockIdx.x;                   // bt*32 + x
    float P[KM], Q[KM];
    const float* pp = g_P + (size_t)bx * KM * E + e;
    const float* qp = g_Q + (size_t)bx * KM * E + e;
    #pragma unroll
    for (int k = 0; k < KM; k++) {
        P[k] = pp[(size_t)k * E];
        Q[k] = qp[(size_t)k * E];
    }
    for (int y = 0; y < 32; y++) {
        float acc = 0.f;
        #pragma unroll
        for (int ky = 0; ky < KM; ky++) {
            int m = (ky * y) & 31;
            acc += P[ky] * C[m] - Q[ky] * S[m];
        }
        size_t idx = ((size_t)bx * 32 + y) * E + e;
        g_r1[idx] = acc + g_h[idx] + inp[idx];
    }
}

// ---------------- dense fp32 GEMM: 128x128x8 tile, 256 threads, 8x8 micro ----------------
template<int N_, bool GELU, bool RESID>
__device__ __forceinline__ void gemm_core(const float* __restrict__ A,
                                          const float* __restrict__ Bm,
                                          const float* __restrict__ bias,
                                          const float* __restrict__ res,
                                          float* __restrict__ Cout, int K) {
    __shared__ __align__(16) float As[8][128];
    __shared__ __align__(16) float Bs[8][128];
    int t = threadIdx.x;
    int m0 = blockIdx.y * 128, n0 = blockIdx.x * 128;
    float acc[8][8];
    #pragma unroll
    for (int i = 0; i < 8; i++)
        #pragma unroll
        for (int j = 0; j < 8; j++) acc[i][j] = 0.f;

    int la_r = t >> 1, la_c = (t & 1) * 4;
    int lb_r = t >> 5, lb_c = (t & 31) * 4;
    const float* Ap = A + (size_t)(m0 + la_r) * K + la_c;
    const float* Bp = Bm + (size_t)lb_r * N_ + n0 + lb_c;
    int tm = (t >> 4) << 3, tn = (t & 15) << 3;

    for (int k0 = 0; k0 < K; k0 += 8) {
        float4 av = *(const float4*)(Ap + k0);
        float4 bv = *(const float4*)(Bp + (size_t)k0 * N_);
        As[la_c + 0][la_r] = av.x;
        As[la_c + 1][la_r] = av.y;
        As[la_c + 2][la_r] = av.z;
        As[la_c + 3][la_r] = av.w;
        *(float4*)&Bs[lb_r][lb_c] = bv;
        __syncthreads();
        #pragma unroll
        for (int kk = 0; kk < 8; kk++) {
            float a[8], bb[8];
            *(float4*)(a)      = *(const float4*)(&As[kk][tm]);
            *(float4*)(a + 4)  = *(const float4*)(&As[kk][tm + 4]);
            *(float4*)(bb)     = *(const float4*)(&Bs[kk][tn]);
            *(float4*)(bb + 4) = *(const float4*)(&Bs[kk][tn + 4]);
            #pragma unroll
            for (int i = 0; i < 8; i++)
                #pragma unroll
                for (int j = 0; j < 8; j++)
                    acc[i][j] += a[i] * bb[j];
        }
        __syncthreads();
    }
    #pragma unroll
    for (int i = 0; i < 8; i++) {
        size_t m = m0 + tm + i;
        #pragma unroll
        for (int j = 0; j < 8; j++) {
            int n = n0 + tn + j;
            float v = acc[i][j] + bias[n];
            if (GELU)  v = gelu_f(v);
            if (RESID) v += res[m * N_ + n];
            Cout[m * N_ + n] = v;
        }
    }
}

__global__ void gemm1_kernel(const float* __restrict__ mw1, const float* __restrict__ mb1) {
    gemm_core<HID, true, false>(g_y, mw1, mb1, nullptr, g_mid, E);
}
__global__ void gemm2_kernel(const float* __restrict__ mw2, const float* __restrict__ mb2,
                             float* __restrict__ out) {
    gemm_core<E, false, true>(g_mid, mw2, mb2, g_r1, out, HID);
}

// ---------------- launch ----------------
extern "C" void kernel_launch(void* const* d_in, const int* in_sizes, int n_in,
                              void* d_out, int out_size) {
    const float* inp  = (const float*)d_in[0];
    const float* w1   = (const float*)d_in[1];
    const float* b1   = (const float*)d_in[2];
    const float* w2   = (const float*)d_in[3];
    const float* b2   = (const float*)d_in[4];
    const float* ln1g = (const float*)d_in[5];
    const float* ln1b = (const float*)d_in[6];
    const float* ln2g = (const float*)d_in[7];
    const float* ln2b = (const float*)d_in[8];
    const float* mw1  = (const float*)d_in[9];
    const float* mb1  = (const float*)d_in[10];
    const float* mw2  = (const float*)d_in[11];
    const float* mb2  = (const float*)d_in[12];
    float* out = (float*)d_out;

    ln1_kernel<<<TOK, 256>>>(inp, ln1g, ln1b);
    fwd_y_kernel<<<BT * NXD, 768>>>();
    fwd_x_kernel<<<dim3(BT * KM, 2), 768>>>();
    bmlp_kernel<<<BT * NMODE, 768>>>(w1, b1, w2, b2);
    inv_x_kernel<<<BT * NXD * KM, 768>>>();
    inv_y_kernel<<<BT * NXD, 768>>>(inp);
    ln2_kernel<<<TOK, 256>>>(ln2g, ln2b);
    gemm1_kernel<<<dim3(HID / 128, TOK / 128), 256>>>(mw1, mb1);
    gemm2_kernel<<<dim3(E / 128, TOK / 128), 256>>>(mw2, mb2, out);
}

// round 6
// speedup vs baseline: 2.3376x; 2.3376x over previous
#include <cuda_runtime.h>
#include <math.h>
#include <stdint.h>

// Problem constants
#define BT   16          // B*T
#define E    768
#define NXD  32
#define NYD  32
#define NP   1024        // NX*NY
#define TOK  (BT*NP)     // 16384 tokens
#define KM   12          // kept y modes
#define J24  24          // kept x modes (kx = 5..28)
#define KX0  5
#define NMODE 288        // 24*12
#define HID  3072
#define TWO_PI_32 0.19634954084936207f

// ---------------- scratch (static device allocations; no cudaMalloc) ----------------
__device__ float g_h [TOK*E];          // LN1 output
__device__ float g_U [BT*NXD*KM*E];    // fwd y-DFT real
__device__ float g_V [BT*NXD*KM*E];    // fwd y-DFT imag
__device__ float g_fr[BT*NMODE*E];
__device__ float g_fi[BT*NMODE*E];
__device__ float g_sr[BT*NMODE*E];
__device__ float g_si[BT*NMODE*E];
__device__ float g_P [BT*NXD*KM*E];    // inv x-iDFT real (pre-weighted)
__device__ float g_Q [BT*NXD*KM*E];
__device__ float g_r1[TOK*E];          // spat + h + input  (res2)
__device__ float g_y [TOK*E];          // LN2 output
__device__ float g_mid[(size_t)TOK*HID]; // gelu(y@mw1+mb1)

__device__ __forceinline__ float gelu_f(float x) {
    return 0.5f * x * (1.0f + erff(x * 0.7071067811865475f));
}
__device__ __forceinline__ float softshrink_f(float x) {
    return x > 0.01f ? x - 0.01f : (x < -0.01f ? x + 0.01f : 0.0f);
}
__device__ __forceinline__ float to_tf32(float x) {
    asm("cvt.rna.tf32.f32 %0, %0;" : "+f"(x));
    return x;
}

// ---------------- LayerNorm (one block per token, 256 threads, 3 elems/thread) ----------------
__device__ __forceinline__ void ln_row(const float* __restrict__ xr,
                                       const float* __restrict__ g,
                                       const float* __restrict__ b,
                                       float* __restrict__ orow) {
    int t = threadIdx.x;
    float v0 = xr[t], v1 = xr[t + 256], v2 = xr[t + 512];
    float s  = v0 + v1 + v2;
    float s2 = v0*v0 + v1*v1 + v2*v2;
    #pragma unroll
    for (int o = 16; o > 0; o >>= 1) {
        s  += __shfl_down_sync(0xffffffffu, s,  o);
        s2 += __shfl_down_sync(0xffffffffu, s2, o);
    }
    __shared__ float sa[8], sb[8];
    __shared__ float mS, rS;
    if ((t & 31) == 0) { sa[t >> 5] = s; sb[t >> 5] = s2; }
    __syncthreads();
    if (t == 0) {
        float ts = 0.f, ts2 = 0.f;
        #pragma unroll
        for (int i = 0; i < 8; i++) { ts += sa[i]; ts2 += sb[i]; }
        float m = ts * (1.0f / 768.0f);
        float var = ts2 * (1.0f / 768.0f) - m * m;
        mS = m; rS = rsqrtf(var + 1e-5f);
    }
    __syncthreads();
    float m = mS, r = rS;
    orow[t]       = (v0 - m) * r * g[t]       + b[t];
    orow[t + 256] = (v1 - m) * r * g[t + 256] + b[t + 256];
    orow[t + 512] = (v2 - m) * r * g[t + 512] + b[t + 512];
}

__global__ void ln1_kernel(const float* __restrict__ x,
                           const float* __restrict__ g,
                           const float* __restrict__ b) {
    size_t row = blockIdx.x;
    ln_row(x + row * E, g, b, g_h + row * E);
}
__global__ void ln2_kernel(const float* __restrict__ g,
                           const float* __restrict__ b) {
    size_t row = blockIdx.x;
    ln_row(g_r1 + row * E, g, b, g_y + row * E);
}

// ---------------- forward DFT stage 1 (over y) ----------------
__global__ void fwd_y_kernel() {
    __shared__ float C[32], S[32];
    if (threadIdx.x < 32) {
        float a = threadIdx.x * TWO_PI_32;
        C[threadIdx.x] = cosf(a); S[threadIdx.x] = sinf(a);
    }
    __syncthreads();
    int e = threadIdx.x;
    int bx = blockIdx.x;                    // bt*32 + x
    float U[KM], V[KM];
    #pragma unroll
    for (int k = 0; k < KM; k++) { U[k] = 0.f; V[k] = 0.f; }
    const float* hp = g_h + (size_t)bx * 32 * E + e;
    for (int y = 0; y < 32; y++) {
        float v = hp[(size_t)y * E];
        #pragma unroll
        for (int ky = 0; ky < KM; ky++) {
            int m = (y * ky) & 31;
            U[ky] += v * C[m];
            V[ky] -= v * S[m];
        }
    }
    float* up = g_U + (size_t)bx * KM * E + e;
    float* vp = g_V + (size_t)bx * KM * E + e;
    #pragma unroll
    for (int ky = 0; ky < KM; ky++) {
        up[(size_t)ky * E] = U[ky];
        vp[(size_t)ky * E] = V[ky];
    }
}

// ---------------- forward DFT stage 2 (over x) ----------------
__global__ void fwd_x_kernel() {
    __shared__ float C[32], S[32];
    if (threadIdx.x < 32) {
        float a = threadIdx.x * TWO_PI_32;
        C[threadIdx.x] = cosf(a); S[threadIdx.x] = sinf(a);
    }
    __syncthreads();
    int e  = threadIdx.x;
    int ky = blockIdx.x % KM;
    int bt = blockIdx.x / KM;
    int j0 = blockIdx.y * 12;
    float fr[12], fi[12];
    #pragma unroll
    for (int j = 0; j < 12; j++) { fr[j] = 0.f; fi[j] = 0.f; }
    const float* up = g_U + ((size_t)(bt * 32) * KM + ky) * E + e;
    const float* vp = g_V + ((size_t)(bt * 32) * KM + ky) * E + e;
    for (int x = 0; x < 32; x++) {
        float u = up[(size_t)x * KM * E];
        float v = vp[(size_t)x * KM * E];
        #pragma unroll
        for (int jj = 0; jj < 12; jj++) {
            int kx = j0 + jj + KX0;
            int m = (kx * x) & 31;
            float c = C[m], s = S[m];
            fr[jj] += u * c + v * s;
            fi[jj] += v * c - u * s;
        }
    }
    const float sc = 1.0f / 32.0f;
    #pragma unroll
    for (int jj = 0; jj < 12; jj++) {
        size_t idx = ((size_t)bt * NMODE + (size_t)(j0 + jj) * KM + ky) * E + e;
        g_fr[idx] = fr[jj] * sc;
        g_fi[idx] = fi[jj] * sc;
    }
}

// ---------------- block-diagonal complex MLP ----------------
__global__ void bmlp_kernel(const float* __restrict__ w1, const float* __restrict__ b1,
                            const float* __restrict__ w2, const float* __restrict__ b2) {
    __shared__ float sfr[768], sfi[768], sar[768], sai[768];
    int t = threadIdx.x;
    size_t base = (size_t)blockIdx.x * E;
    sfr[t] = g_fr[base + t];
    sfi[t] = g_fi[base + t];
    __syncthreads();
    int n = t >> 6, oi = t & 63;

    const float* w0p = w1 + ((size_t)n * 64) * 64 + oi;
    const float* w1p = w1 + ((size_t)(12 + n) * 64) * 64 + oi;
    const float* frb = sfr + n * 64;
    const float* fib = sfi + n * 64;
    float ar = b1[t];
    float ai = b1[768 + t];
    #pragma unroll 8
    for (int i = 0; i < 64; i++) {
        float a = w0p[(size_t)i * 64];
        float bb = w1p[(size_t)i * 64];
        float fr = frb[i], fi = fib[i];
        ar += fr * a - fi * bb;
        ai += fi * a + fr * bb;
    }
    sar[t] = gelu_f(ar);
    sai[t] = gelu_f(ai);
    __syncthreads();

    const float* u0p = w2 + ((size_t)n * 64) * 64 + oi;
    const float* u1p = w2 + ((size_t)(12 + n) * 64) * 64 + oi;
    const float* orb = sar + n * 64;
    const float* oib = sai + n * 64;
    float cr = b2[t];
    float ci = b2[768 + t];
    #pragma unroll 8
    for (int i = 0; i < 64; i++) {
        float a = u0p[(size_t)i * 64];
        float bb = u1p[(size_t)i * 64];
        float orr = orb[i], oii = oib[i];
        cr += orr * a - oii * bb;
        ci += oii * a + orr * bb;
    }
    g_sr[base + t] = softshrink_f(cr);
    g_si[base + t] = softshrink_f(ci);
}

// ---------------- inverse stage 1 (over kx) ----------------
__global__ void inv_x_kernel() {
    __shared__ float C[32], S[32];
    if (threadIdx.x < 32) {
        float a = threadIdx.x * TWO_PI_32;
        C[threadIdx.x] = cosf(a); S[threadIdx.x] = sinf(a);
    }
    __syncthreads();
    int e  = threadIdx.x;
    int bx = blockIdx.x;
    int ky = bx % KM;
    int x  = (bx / KM) % 32;
    int bt = bx / (32 * KM);
    float P = 0.f, Q = 0.f;
    const float* srp = g_sr + ((size_t)bt * NMODE + ky) * E + e;
    const float* sip = g_si + ((size_t)bt * NMODE + ky) * E + e;
    #pragma unroll 4
    for (int j = 0; j < J24; j++) {
        float sr = srp[(size_t)j * KM * E];
        float si = sip[(size_t)j * KM * E];
        int m = ((j + KX0) * x) & 31;
        float c = C[m], s = S[m];
        P += sr * c - si * s;
        Q += sr * s + si * c;
    }
    float wgt = (ky == 0 ? 1.0f : 2.0f) * (1.0f / 32.0f);
    size_t idx = ((size_t)(bt * 32 + x) * KM + ky) * E + e;
    g_P[idx] = P * wgt;
    g_Q[idx] = Q * wgt;
}

// ---------------- inverse stage 2 (over ky) + residual adds ----------------
__global__ void inv_y_kernel(const float* __restrict__ inp) {
    __shared__ float C[32], S[32];
    if (threadIdx.x < 32) {
        float a = threadIdx.x * TWO_PI_32;
        C[threadIdx.x] = cosf(a); S[threadIdx.x] = sinf(a);
    }
    __syncthreads();
    int e = threadIdx.x;
    int bx = blockIdx.x;                   // bt*32 + x
    float P[KM], Q[KM];
    const float* pp = g_P + (size_t)bx * KM * E + e;
    const float* qp = g_Q + (size_t)bx * KM * E + e;
    #pragma unroll
    for (int k = 0; k < KM; k++) {
        P[k] = pp[(size_t)k * E];
        Q[k] = qp[(size_t)k * E];
    }
    for (int y = 0; y < 32; y++) {
        float acc = 0.f;
        #pragma unroll
        for (int ky = 0; ky < KM; ky++) {
            int m = (ky * y) & 31;
            acc += P[ky] * C[m] - Q[ky] * S[m];
        }
        size_t idx = ((size_t)bx * 32 + y) * E + e;
        g_r1[idx] = acc + g_h[idx] + inp[idx];
    }
}

// ======================================================================
//  TF32 tensor-core GEMM: 128x128 block tile, 8 warps, warp tile 64x32,
//  mma.m16n8k8, BK=16, double-buffered SMEM.
// ======================================================================
#define BM 128
#define BN 128
#define BK 16
#define ASTR 20     // As [m][k] stride (conflict-free fragment loads)
#define BSTR 132    // Bs [k][n] stride

__device__ __forceinline__ void mma_tf32(float* c, const uint32_t* a, const uint32_t* b) {
    asm volatile(
        "mma.sync.aligned.m16n8k8.row.col.f32.tf32.tf32.f32 "
        "{%0,%1,%2,%3}, {%4,%5,%6,%7}, {%8,%9}, {%0,%1,%2,%3};\n"
        : "+f"(c[0]), "+f"(c[1]), "+f"(c[2]), "+f"(c[3])
        : "r"(a[0]), "r"(a[1]), "r"(a[2]), "r"(a[3]), "r"(b[0]), "r"(b[1]));
}

template<int N_, bool GELU, bool RESID>
__device__ __forceinline__ void gemm_tc_core(const float* __restrict__ A,
                                             const float* __restrict__ Bm,
                                             const float* __restrict__ bias,
                                             const float* __restrict__ res,
                                             float* __restrict__ Cout, int K) {
    __shared__ float As[2][BM * ASTR];
    __shared__ float Bs[2][BK * BSTR];

    int t = threadIdx.x;
    int lane = t & 31, wid = t >> 5;
    int gid = lane >> 2, tig = lane & 3;
    int wm = (wid & 1) * 64;            // 2 warps along M
    int wn = (wid >> 1) * 32;           // 4 warps along N
    int m0 = blockIdx.y * BM, n0 = blockIdx.x * BN;

    float acc[4][4][4];
    #pragma unroll
    for (int i = 0; i < 4; i++)
        #pragma unroll
        for (int j = 0; j < 4; j++)
            #pragma unroll
            for (int k = 0; k < 4; k++) acc[i][j][k] = 0.f;

    // global->smem mapping
    int ar = t >> 2;                    // 0..63  (A rows; +64 for second)
    int ac = (t & 3) * 4;               // k offset within tile
    int bk = t >> 5;                    // 0..7   (B k rows; +8 for second)
    int bc = (t & 31) * 4;              // n offset
    const float* Ap0 = A + (size_t)(m0 + ar) * K + ac;
    const float* Ap1 = A + (size_t)(m0 + ar + 64) * K + ac;
    const float* Bp0 = Bm + (size_t)bk * N_ + n0 + bc;
    const float* Bp1 = Bm + (size_t)(bk + 8) * N_ + n0 + bc;

    int NT = K / BK;

    // prologue: tile 0
    {
        float4 a0 = *(const float4*)(Ap0);
        float4 a1 = *(const float4*)(Ap1);
        float4 b0 = *(const float4*)(Bp0);
        float4 b1 = *(const float4*)(Bp1);
        float* As_ = As[0]; float* Bs_ = Bs[0];
        As_[ar * ASTR + ac + 0] = to_tf32(a0.x);
        As_[ar * ASTR + ac + 1] = to_tf32(a0.y);
        As_[ar * ASTR + ac + 2] = to_tf32(a0.z);
        As_[ar * ASTR + ac + 3] = to_tf32(a0.w);
        As_[(ar + 64) * ASTR + ac + 0] = to_tf32(a1.x);
        As_[(ar + 64) * ASTR + ac + 1] = to_tf32(a1.y);
        As_[(ar + 64) * ASTR + ac + 2] = to_tf32(a1.z);
        As_[(ar + 64) * ASTR + ac + 3] = to_tf32(a1.w);
        Bs_[bk * BSTR + bc + 0] = to_tf32(b0.x);
        Bs_[bk * BSTR + bc + 1] = to_tf32(b0.y);
        Bs_[bk * BSTR + bc + 2] = to_tf32(b0.z);
        Bs_[bk * BSTR + bc + 3] = to_tf32(b0.w);
        Bs_[(bk + 8) * BSTR + bc + 0] = to_tf32(b1.x);
        Bs_[(bk + 8) * BSTR + bc + 1] = to_tf32(b1.y);
        Bs_[(bk + 8) * BSTR + bc + 2] = to_tf32(b1.z);
        Bs_[(bk + 8) * BSTR + bc + 3] = to_tf32(b1.w);
    }
    __syncthreads();

    for (int kt = 0; kt < NT; kt++) {
        float4 a0, a1, b0, b1;
        bool has = (kt + 1) < NT;
        if (has) {
            int k0 = (kt + 1) * BK;
            a0 = *(const float4*)(Ap0 + k0);
            a1 = *(const float4*)(Ap1 + k0);
            b0 = *(const float4*)(Bp0 + (size_t)k0 * N_);
            b1 = *(const float4*)(Bp1 + (size_t)k0 * N_);
        }

        const float* Asb = As[kt & 1];
        const float* Bsb = Bs[kt & 1];
        #pragma unroll
        for (int ka = 0; ka < 2; ka++) {
            int kf = ka * 8 + tig;
            uint32_t af[4][4];
            #pragma unroll
            for (int ma = 0; ma < 4; ma++) {
                int r = wm + ma * 16 + gid;
                af[ma][0] = __float_as_uint(Asb[r * ASTR + kf]);
                af[ma][1] = __float_as_uint(Asb[(r + 8) * ASTR + kf]);
                af[ma][2] = __float_as_uint(Asb[r * ASTR + kf + 4]);
                af[ma][3] = __float_as_uint(Asb[(r + 8) * ASTR + kf + 4]);
            }
            uint32_t bf[4][2];
            #pragma unroll
            for (int na = 0; na < 4; na++) {
                int c = wn + na * 8 + gid;
                bf[na][0] = __float_as_uint(Bsb[kf * BSTR + c]);
                bf[na][1] = __float_as_uint(Bsb[(kf + 4) * BSTR + c]);
            }
            #pragma unroll
            for (int ma = 0; ma < 4; ma++)
                #pragma unroll
                for (int na = 0; na < 4; na++)
                    mma_tf32(acc[ma][na], af[ma], bf[na]);
        }

        if (has) {
            float* As_ = As[(kt + 1) & 1];
            float* Bs_ = Bs[(kt + 1) & 1];
            As_[ar * ASTR + ac + 0] = to_tf32(a0.x);
            As_[ar * ASTR + ac + 1] = to_tf32(a0.y);
            As_[ar * ASTR + ac + 2] = to_tf32(a0.z);
            As_[ar * ASTR + ac + 3] = to_tf32(a0.w);
            As_[(ar + 64) * ASTR + ac + 0] = to_tf32(a1.x);
            As_[(ar + 64) * ASTR + ac + 1] = to_tf32(a1.y);
            As_[(ar + 64) * ASTR + ac + 2] = to_tf32(a1.z);
            As_[(ar + 64) * ASTR + ac + 3] = to_tf32(a1.w);
            Bs_[bk * BSTR + bc + 0] = to_tf32(b0.x);
            Bs_[bk * BSTR + bc + 1] = to_tf32(b0.y);
            Bs_[bk * BSTR + bc + 2] = to_tf32(b0.z);
            Bs_[bk * BSTR + bc + 3] = to_tf32(b0.w);
            Bs_[(bk + 8) * BSTR + bc + 0] = to_tf32(b1.x);
            Bs_[(bk + 8) * BSTR + bc + 1] = to_tf32(b1.y);
            Bs_[(bk + 8) * BSTR + bc + 2] = to_tf32(b1.z);
            Bs_[(bk + 8) * BSTR + bc + 3] = to_tf32(b1.w);
        }
        __syncthreads();
    }

    // epilogue
    #pragma unroll
    for (int ma = 0; ma < 4; ma++) {
        size_t r = m0 + wm + ma * 16 + gid;
        #pragma unroll
        for (int na = 0; na < 4; na++) {
            int c = n0 + wn + na * 8 + tig * 2;
            float v0 = acc[ma][na][0] + bias[c];
            float v1 = acc[ma][na][1] + bias[c + 1];
            float v2 = acc[ma][na][2] + bias[c];
            float v3 = acc[ma][na][3] + bias[c + 1];
            if (GELU) { v0 = gelu_f(v0); v1 = gelu_f(v1); v2 = gelu_f(v2); v3 = gelu_f(v3); }
            if (RESID) {
                float2 r0 = *(const float2*)(res + r * N_ + c);
                float2 r1 = *(const float2*)(res + (r + 8) * N_ + c);
                v0 += r0.x; v1 += r0.y; v2 += r1.x; v3 += r1.y;
            }
            *(float2*)(Cout + r * N_ + c) = make_float2(v0, v1);
            *(float2*)(Cout + (r + 8) * N_ + c) = make_float2(v2, v3);
        }
    }
}

__global__ __launch_bounds__(256, 2) void gemm1_tc_kernel(const float* __restrict__ mw1,
                                                          const float* __restrict__ mb1) {
    gemm_tc_core<HID, true, false>(g_y, mw1, mb1, nullptr, g_mid, E);
}
__global__ __launch_bounds__(256, 2) void gemm2_tc_kernel(const float* __restrict__ mw2,
                                                          const float* __restrict__ mb2,
                                                          float* __restrict__ out) {
    gemm_tc_core<E, false, true>(g_mid, mw2, mb2, g_r1, out, HID);
}

// ---------------- launch ----------------
extern "C" void kernel_launch(void* const* d_in, const int* in_sizes, int n_in,
                              void* d_out, int out_size) {
    const float* inp  = (const float*)d_in[0];
    const float* w1   = (const float*)d_in[1];
    const float* b1   = (const float*)d_in[2];
    const float* w2   = (const float*)d_in[3];
    const float* b2   = (const float*)d_in[4];
    const float* ln1g = (const float*)d_in[5];
    const float* ln1b = (const float*)d_in[6];
    const float* ln2g = (const float*)d_in[7];
    const float* ln2b = (const float*)d_in[8];
    const float* mw1  = (const float*)d_in[9];
    const float* mb1  = (const float*)d_in[10];
    const float* mw2  = (const float*)d_in[11];
    const float* mb2  = (const float*)d_in[12];
    float* out = (float*)d_out;

    ln1_kernel<<<TOK, 256>>>(inp, ln1g, ln1b);
    fwd_y_kernel<<<BT * NXD, 768>>>();
    fwd_x_kernel<<<dim3(BT * KM, 2), 768>>>();
    bmlp_kernel<<<BT * NMODE, 768>>>(w1, b1, w2, b2);
    inv_x_kernel<<<BT * NXD * KM, 768>>>();
    inv_y_kernel<<<BT * NXD, 768>>>(inp);
    ln2_kernel<<<TOK, 256>>>(ln2g, ln2b);
    gemm1_tc_kernel<<<dim3(HID / BN, TOK / BM), 256>>>(mw1, mb1);
    gemm2_tc_kernel<<<dim3(E / BN, TOK / BM), 256>>>(mw2, mb2, out);
}

// round 11
// speedup vs baseline: 2.4197x; 1.0351x over previous
#include <cuda_runtime.h>
#include <math.h>
#include <stdint.h>

// Problem constants
#define BT   16          // B*T
#define E    768
#define NXD  32
#define NYD  32
#define NP   1024        // NX*NY
#define TOK  (BT*NP)     // 16384 tokens
#define KM   12          // kept y modes
#define J24  24          // kept x modes (kx = 5..28)
#define KX0  5
#define NMODE 288        // 24*12
#define HID  3072
#define TWO_PI_32 0.19634954084936207f

// ---------------- scratch (static device allocations; no cudaMalloc) ----------------
__device__ float g_h [TOK*E];          // LN1 output
__device__ float g_U [BT*NXD*KM*E];    // fwd y-DFT real
__device__ float g_V [BT*NXD*KM*E];    // fwd y-DFT imag
__device__ float g_fr[BT*NMODE*E];
__device__ float g_fi[BT*NMODE*E];
__device__ float g_sr[BT*NMODE*E];
__device__ float g_si[BT*NMODE*E];
__device__ float g_P [BT*NXD*KM*E];    // inv x-iDFT real (pre-weighted)
__device__ float g_Q [BT*NXD*KM*E];
__device__ float g_r1[TOK*E];          // spat + h + input  (res2)
__device__ float g_y [TOK*E];          // LN2 output
__device__ float g_mid[(size_t)TOK*HID]; // gelu(y@mw1+mb1)

__device__ __forceinline__ float gelu_f(float x) {
    return 0.5f * x * (1.0f + erff(x * 0.7071067811865475f));
}
__device__ __forceinline__ float softshrink_f(float x) {
    return x > 0.01f ? x - 0.01f : (x < -0.01f ? x + 0.01f : 0.0f);
}
__device__ __forceinline__ float to_tf32(float x) {
    asm("cvt.rna.tf32.f32 %0, %0;" : "+f"(x));
    return x;
}

// ---------------- LayerNorm (one block per token, 256 threads, 3 elems/thread) ----------------
__device__ __forceinline__ void ln_row(const float* __restrict__ xr,
                                       const float* __restrict__ g,
                                       const float* __restrict__ b,
                                       float* __restrict__ orow) {
    int t = threadIdx.x;
    float v0 = xr[t], v1 = xr[t + 256], v2 = xr[t + 512];
    float s  = v0 + v1 + v2;
    float s2 = v0*v0 + v1*v1 + v2*v2;
    #pragma unroll
    for (int o = 16; o > 0; o >>= 1) {
        s  += __shfl_down_sync(0xffffffffu, s,  o);
        s2 += __shfl_down_sync(0xffffffffu, s2, o);
    }
    __shared__ float sa[8], sb[8];
    __shared__ float mS, rS;
    if ((t & 31) == 0) { sa[t >> 5] = s; sb[t >> 5] = s2; }
    __syncthreads();
    if (t == 0) {
        float ts = 0.f, ts2 = 0.f;
        #pragma unroll
        for (int i = 0; i < 8; i++) { ts += sa[i]; ts2 += sb[i]; }
        float m = ts * (1.0f / 768.0f);
        float var = ts2 * (1.0f / 768.0f) - m * m;
        mS = m; rS = rsqrtf(var + 1e-5f);
    }
    __syncthreads();
    float m = mS, r = rS;
    orow[t]       = (v0 - m) * r * g[t]       + b[t];
    orow[t + 256] = (v1 - m) * r * g[t + 256] + b[t + 256];
    orow[t + 512] = (v2 - m) * r * g[t + 512] + b[t + 512];
}

__global__ void ln1_kernel(const float* __restrict__ x,
                           const float* __restrict__ g,
                           const float* __restrict__ b) {
    size_t row = blockIdx.x;
    ln_row(x + row * E, g, b, g_h + row * E);
}
__global__ void ln2_kernel(const float* __restrict__ g,
                           const float* __restrict__ b) {
    size_t row = blockIdx.x;
    ln_row(g_r1 + row * E, g, b, g_y + row * E);
}

// ---------------- forward DFT stage 1 (over y) ----------------
__global__ void fwd_y_kernel() {
    __shared__ float C[32], S[32];
    if (threadIdx.x < 32) {
        float a = threadIdx.x * TWO_PI_32;
        C[threadIdx.x] = cosf(a); S[threadIdx.x] = sinf(a);
    }
    __syncthreads();
    int e = threadIdx.x;
    int bx = blockIdx.x;                    // bt*32 + x
    float U[KM], V[KM];
    #pragma unroll
    for (int k = 0; k < KM; k++) { U[k] = 0.f; V[k] = 0.f; }
    const float* hp = g_h + (size_t)bx * 32 * E + e;
    for (int y = 0; y < 32; y++) {
        float v = hp[(size_t)y * E];
        #pragma unroll
        for (int ky = 0; ky < KM; ky++) {
            int m = (y * ky) & 31;
            U[ky] += v * C[m];
            V[ky] -= v * S[m];
        }
    }
    float* up = g_U + (size_t)bx * KM * E + e;
    float* vp = g_V + (size_t)bx * KM * E + e;
    #pragma unroll
    for (int ky = 0; ky < KM; ky++) {
        up[(size_t)ky * E] = U[ky];
        vp[(size_t)ky * E] = V[ky];
    }
}

// ---------------- forward DFT stage 2 (over x) ----------------
__global__ void fwd_x_kernel() {
    __shared__ float C[32], S[32];
    if (threadIdx.x < 32) {
        float a = threadIdx.x * TWO_PI_32;
        C[threadIdx.x] = cosf(a); S[threadIdx.x] = sinf(a);
    }
    __syncthreads();
    int e  = threadIdx.x;
    int ky = blockIdx.x % KM;
    int bt = blockIdx.x / KM;
    int j0 = blockIdx.y * 12;
    float fr[12], fi[12];
    #pragma unroll
    for (int j = 0; j < 12; j++) { fr[j] = 0.f; fi[j] = 0.f; }
    const float* up = g_U + ((size_t)(bt * 32) * KM + ky) * E + e;
    const float* vp = g_V + ((size_t)(bt * 32) * KM + ky) * E + e;
    for (int x = 0; x < 32; x++) {
        float u = up[(size_t)x * KM * E];
        float v = vp[(size_t)x * KM * E];
        #pragma unroll
        for (int jj = 0; jj < 12; jj++) {
            int kx = j0 + jj + KX0;
            int m = (kx * x) & 31;
            float c = C[m], s = S[m];
            fr[jj] += u * c + v * s;
            fi[jj] += v * c - u * s;
        }
    }
    const float sc = 1.0f / 32.0f;
    #pragma unroll
    for (int jj = 0; jj < 12; jj++) {
        size_t idx = ((size_t)bt * NMODE + (size_t)(j0 + jj) * KM + ky) * E + e;
        g_fr[idx] = fr[jj] * sc;
        g_fi[idx] = fi[jj] * sc;
    }
}

// ---------------- block-diagonal complex MLP (4 mode-positions per block) ----------------
// smem reuse: sfr/sfi hold inputs for layer1, then gelu(layer1) for layer2. 24KB.
#define MPB 4
__global__ void bmlp_kernel(const float* __restrict__ w1, const float* __restrict__ b1,
                            const float* __restrict__ w2, const float* __restrict__ b2) {
    __shared__ float sfr[MPB][768], sfi[MPB][768];
    int t = threadIdx.x;
    size_t base = (size_t)blockIdx.x * MPB * E;
    #pragma unroll
    for (int m = 0; m < MPB; m++) {
        sfr[m][t] = g_fr[base + (size_t)m * E + t];
        sfi[m][t] = g_fi[base + (size_t)m * E + t];
    }
    __syncthreads();
    int n = t >> 6;

    // layer 1 (accumulate in registers)
    const float* w0p = w1 + ((size_t)n * 64) * 64 + (t & 63);
    const float* w1p = w1 + ((size_t)(12 + n) * 64) * 64 + (t & 63);
    float ar[MPB], ai[MPB];
    float bre = b1[t], bim = b1[768 + t];
    #pragma unroll
    for (int m = 0; m < MPB; m++) { ar[m] = bre; ai[m] = bim; }
    #pragma unroll 8
    for (int i = 0; i < 64; i++) {
        float a  = w0p[(size_t)i * 64];
        float bb = w1p[(size_t)i * 64];
        #pragma unroll
        for (int m = 0; m < MPB; m++) {
            float fr = sfr[m][n * 64 + i], fi = sfi[m][n * 64 + i];
            ar[m] += fr * a - fi * bb;
            ai[m] += fi * a + fr * bb;
        }
    }
    __syncthreads();                    // all layer-1 reads complete
    #pragma unroll
    for (int m = 0; m < MPB; m++) {
        sfr[m][t] = gelu_f(ar[m]);
        sfi[m][t] = gelu_f(ai[m]);
    }
    __syncthreads();

    // layer 2 + softshrink
    const float* u0p = w2 + ((size_t)n * 64) * 64 + (t & 63);
    const float* u1p = w2 + ((size_t)(12 + n) * 64) * 64 + (t & 63);
    float cr[MPB], ci[MPB];
    float cre = b2[t], cim = b2[768 + t];
    #pragma unroll
    for (int m = 0; m < MPB; m++) { cr[m] = cre; ci[m] = cim; }
    #pragma unroll 8
    for (int i = 0; i < 64; i++) {
        float a  = u0p[(size_t)i * 64];
        float bb = u1p[(size_t)i * 64];
        #pragma unroll
        for (int m = 0; m < MPB; m++) {
            float orr = sfr[m][n * 64 + i], oii = sfi[m][n * 64 + i];
            cr[m] += orr * a - oii * bb;
            ci[m] += oii * a + orr * bb;
        }
    }
    #pragma unroll
    for (int m = 0; m < MPB; m++) {
        g_sr[base + (size_t)m * E + t] = softshrink_f(cr[m]);
        g_si[base + (size_t)m * E + t] = softshrink_f(ci[m]);
    }
}

// ---------------- inverse stage 1 (over kx) ----------------
__global__ void inv_x_kernel() {
    __shared__ float C[32], S[32];
    if (threadIdx.x < 32) {
        float a = threadIdx.x * TWO_PI_32;
        C[threadIdx.x] = cosf(a); S[threadIdx.x] = sinf(a);
    }
    __syncthreads();
    int e  = threadIdx.x;
    int bx = blockIdx.x;
    int ky = bx % KM;
    int x  = (bx / KM) % 32;
    int bt = bx / (32 * KM);
    float P = 0.f, Q = 0.f;
    const float* srp = g_sr + ((size_t)bt * NMODE + ky) * E + e;
    const float* sip = g_si + ((size_t)bt * NMODE + ky) * E + e;
    #pragma unroll 4
    for (int j = 0; j < J24; j++) {
        float sr = srp[(size_t)j * KM * E];
        float si = sip[(size_t)j * KM * E];
        int m = ((j + KX0) * x) & 31;
        float c = C[m], s = S[m];
        P += sr * c - si * s;
        Q += sr * s + si * c;
    }
    float wgt = (ky == 0 ? 1.0f : 2.0f) * (1.0f / 32.0f);
    size_t idx = ((size_t)(bt * 32 + x) * KM + ky) * E + e;
    g_P[idx] = P * wgt;
    g_Q[idx] = Q * wgt;
}

// ---------------- inverse stage 2 (over ky) + residual adds ----------------
__global__ void inv_y_kernel(const float* __restrict__ inp) {
    __shared__ float C[32], S[32];
    if (threadIdx.x < 32) {
        float a = threadIdx.x * TWO_PI_32;
        C[threadIdx.x] = cosf(a); S[threadIdx.x] = sinf(a);
    }
    __syncthreads();
    int e = threadIdx.x;
    int bx = blockIdx.x;                   // bt*32 + x
    float P[KM], Q[KM];
    const float* pp = g_P + (size_t)bx * KM * E + e;
    const float* qp = g_Q + (size_t)bx * KM * E + e;
    #pragma unroll
    for (int k = 0; k < KM; k++) {
        P[k] = pp[(size_t)k * E];
        Q[k] = qp[(size_t)k * E];
    }
    for (int y = 0; y < 32; y++) {
        float acc = 0.f;
        #pragma unroll
        for (int ky = 0; ky < KM; ky++) {
            int m = (ky * y) & 31;
            acc += P[ky] * C[m] - Q[ky] * S[m];
        }
        size_t idx = ((size_t)bx * 32 + y) * E + e;
        g_r1[idx] = acc + g_h[idx] + inp[idx];
    }
}

// ======================================================================
//  TF32 tensor-core GEMM (PROVEN in R6): 128x128 block tile, 8 warps,
//  warp tile 64x32, mma.m16n8k8, BK=16, double-buffered SMEM.
// ======================================================================
#define BM 128
#define BN 128
#define BK 16
#define ASTR 20     // As [m][k] stride (conflict-free fragment loads)
#define BSTR 132    // Bs [k][n] stride

__device__ __forceinline__ void mma_tf32(float* c, const uint32_t* a, const uint32_t* b) {
    asm volatile(
        "mma.sync.aligned.m16n8k8.row.col.f32.tf32.tf32.f32 "
        "{%0,%1,%2,%3}, {%4,%5,%6,%7}, {%8,%9}, {%0,%1,%2,%3};\n"
        : "+f"(c[0]), "+f"(c[1]), "+f"(c[2]), "+f"(c[3])
        : "r"(a[0]), "r"(a[1]), "r"(a[2]), "r"(a[3]), "r"(b[0]), "r"(b[1]));
}

template<int N_, bool GELU, bool RESID>
__device__ __forceinline__ void gemm_tc_core(const float* __restrict__ A,
                                             const float* __restrict__ Bm,
                                             const float* __restrict__ bias,
                                             const float* __restrict__ res,
                                             float* __restrict__ Cout, int K) {
    __shared__ float As[2][BM * ASTR];
    __shared__ float Bs[2][BK * BSTR];

    int t = threadIdx.x;
    int lane = t & 31, wid = t >> 5;
    int gid = lane >> 2, tig = lane & 3;
    int wm = (wid & 1) * 64;            // 2 warps along M
    int wn = (wid >> 1) * 32;           // 4 warps along N
    int m0 = blockIdx.y * BM, n0 = blockIdx.x * BN;

    float acc[4][4][4];
    #pragma unroll
    for (int i = 0; i < 4; i++)
        #pragma unroll
        for (int j = 0; j < 4; j++)
            #pragma unroll
            for (int k = 0; k < 4; k++) acc[i][j][k] = 0.f;

    // global->smem mapping
    int ar = t >> 2;                    // 0..63  (A rows; +64 for second)
    int ac = (t & 3) * 4;               // k offset within tile
    int bk = t >> 5;                    // 0..7   (B k rows; +8 for second)
    int bc = (t & 31) * 4;              // n offset
    const float* Ap0 = A + (size_t)(m0 + ar) * K + ac;
    const float* Ap1 = A + (size_t)(m0 + ar + 64) * K + ac;
    const float* Bp0 = Bm + (size_t)bk * N_ + n0 + bc;
    const float* Bp1 = Bm + (size_t)(bk + 8) * N_ + n0 + bc;

    int NT = K / BK;

    // prologue: tile 0
    {
        float4 a0 = *(const float4*)(Ap0);
        float4 a1 = *(const float4*)(Ap1);
        float4 b0 = *(const float4*)(Bp0);
        float4 b1 = *(const float4*)(Bp1);
        float* As_ = As[0]; float* Bs_ = Bs[0];
        As_[ar * ASTR + ac + 0] = to_tf32(a0.x);
        As_[ar * ASTR + ac + 1] = to_tf32(a0.y);
        As_[ar * ASTR + ac + 2] = to_tf32(a0.z);
        As_[ar * ASTR + ac + 3] = to_tf32(a0.w);
        As_[(ar + 64) * ASTR + ac + 0] = to_tf32(a1.x);
        As_[(ar + 64) * ASTR + ac + 1] = to_tf32(a1.y);
        As_[(ar + 64) * ASTR + ac + 2] = to_tf32(a1.z);
        As_[(ar + 64) * ASTR + ac + 3] = to_tf32(a1.w);
        Bs_[bk * BSTR + bc + 0] = to_tf32(b0.x);
        Bs_[bk * BSTR + bc + 1] = to_tf32(b0.y);
        Bs_[bk * BSTR + bc + 2] = to_tf32(b0.z);
        Bs_[bk * BSTR + bc + 3] = to_tf32(b0.w);
        Bs_[(bk + 8) * BSTR + bc + 0] = to_tf32(b1.x);
        Bs_[(bk + 8) * BSTR + bc + 1] = to_tf32(b1.y);
        Bs_[(bk + 8) * BSTR + bc + 2] = to_tf32(b1.z);
        Bs_[(bk + 8) * BSTR + bc + 3] = to_tf32(b1.w);
    }
    __syncthreads();

    for (int kt = 0; kt < NT; kt++) {
        float4 a0, a1, b0, b1;
        bool has = (kt + 1) < NT;
        if (has) {
            int k0 = (kt + 1) * BK;
            a0 = *(const float4*)(Ap0 + k0);
            a1 = *(const float4*)(Ap1 + k0);
            b0 = *(const float4*)(Bp0 + (size_t)k0 * N_);
            b1 = *(const float4*)(Bp1 + (size_t)k0 * N_);
        }

        const float* Asb = As[kt & 1];
        const float* Bsb = Bs[kt & 1];
        #pragma unroll
        for (int ka = 0; ka < 2; ka++) {
            int kf = ka * 8 + tig;
            uint32_t af[4][4];
            #pragma unroll
            for (int ma = 0; ma < 4; ma++) {
                int r = wm + ma * 16 + gid;
                af[ma][0] = __float_as_uint(Asb[r * ASTR + kf]);
                af[ma][1] = __float_as_uint(Asb[(r + 8) * ASTR + kf]);
                af[ma][2] = __float_as_uint(Asb[r * ASTR + kf + 4]);
                af[ma][3] = __float_as_uint(Asb[(r + 8) * ASTR + kf + 4]);
            }
            uint32_t bf[4][2];
            #pragma unroll
            for (int na = 0; na < 4; na++) {
                int c = wn + na * 8 + gid;
                bf[na][0] = __float_as_uint(Bsb[kf * BSTR + c]);
                bf[na][1] = __float_as_uint(Bsb[(kf + 4) * BSTR + c]);
            }
            #pragma unroll
            for (int ma = 0; ma < 4; ma++)
                #pragma unroll
                for (int na = 0; na < 4; na++)
                    mma_tf32(acc[ma][na], af[ma], bf[na]);
        }

        if (has) {
            float* As_ = As[(kt + 1) & 1];
            float* Bs_ = Bs[(kt + 1) & 1];
            As_[ar * ASTR + ac + 0] = to_tf32(a0.x);
            As_[ar * ASTR + ac + 1] = to_tf32(a0.y);
            As_[ar * ASTR + ac + 2] = to_tf32(a0.z);
            As_[ar * ASTR + ac + 3] = to_tf32(a0.w);
            As_[(ar + 64) * ASTR + ac + 0] = to_tf32(a1.x);
            As_[(ar + 64) * ASTR + ac + 1] = to_tf32(a1.y);
            As_[(ar + 64) * ASTR + ac + 2] = to_tf32(a1.z);
            As_[(ar + 64) * ASTR + ac + 3] = to_tf32(a1.w);
            Bs_[bk * BSTR + bc + 0] = to_tf32(b0.x);
            Bs_[bk * BSTR + bc + 1] = to_tf32(b0.y);
            Bs_[bk * BSTR + bc + 2] = to_tf32(b0.z);
            Bs_[bk * BSTR + bc + 3] = to_tf32(b0.w);
            Bs_[(bk + 8) * BSTR + bc + 0] = to_tf32(b1.x);
            Bs_[(bk + 8) * BSTR + bc + 1] = to_tf32(b1.y);
            Bs_[(bk + 8) * BSTR + bc + 2] = to_tf32(b1.z);
            Bs_[(bk + 8) * BSTR + bc + 3] = to_tf32(b1.w);
        }
        __syncthreads();
    }

    // epilogue
    #pragma unroll
    for (int ma = 0; ma < 4; ma++) {
        size_t r = m0 + wm + ma * 16 + gid;
        #pragma unroll
        for (int na = 0; na < 4; na++) {
            int c = n0 + wn + na * 8 + tig * 2;
            float v0 = acc[ma][na][0] + bias[c];
            float v1 = acc[ma][na][1] + bias[c + 1];
            float v2 = acc[ma][na][2] + bias[c];
            float v3 = acc[ma][na][3] + bias[c + 1];
            if (GELU) { v0 = gelu_f(v0); v1 = gelu_f(v1); v2 = gelu_f(v2); v3 = gelu_f(v3); }
            if (RESID) {
                float2 r0 = *(const float2*)(res + r * N_ + c);
                float2 r1 = *(const float2*)(res + (r + 8) * N_ + c);
                v0 += r0.x; v1 += r0.y; v2 += r1.x; v3 += r1.y;
            }
            *(float2*)(Cout + r * N_ + c) = make_float2(v0, v1);
            *(float2*)(Cout + (r + 8) * N_ + c) = make_float2(v2, v3);
        }
    }
}

__global__ __launch_bounds__(256, 2) void gemm1_tc_kernel(const float* __restrict__ mw1,
                                                          const float* __restrict__ mb1) {
    gemm_tc_core<HID, true, false>(g_y, mw1, mb1, nullptr, g_mid, E);
}
__global__ __launch_bounds__(256, 2) void gemm2_tc_kernel(const float* __restrict__ mw2,
                                                          const float* __restrict__ mb2,
                                                          float* __restrict__ out) {
    gemm_tc_core<E, false, true>(g_mid, mw2, mb2, g_r1, out, HID);
}

// ---------------- launch ----------------
extern "C" void kernel_launch(void* const* d_in, const int* in_sizes, int n_in,
                              void* d_out, int out_size) {
    const float* inp  = (const float*)d_in[0];
    const float* w1   = (const float*)d_in[1];
    const float* b1   = (const float*)d_in[2];
    const float* w2   = (const float*)d_in[3];
    const float* b2   = (const float*)d_in[4];
    const float* ln1g = (const float*)d_in[5];
    const float* ln1b = (const float*)d_in[6];
    const float* ln2g = (const float*)d_in[7];
    const float* ln2b = (const float*)d_in[8];
    const float* mw1  = (const float*)d_in[9];
    const float* mb1  = (const float*)d_in[10];
    const float* mw2  = (const float*)d_in[11];
    const float* mb2  = (const float*)d_in[12];
    float* out = (float*)d_out;

    ln1_kernel<<<TOK, 256>>>(inp, ln1g, ln1b);
    fwd_y_kernel<<<BT * NXD, 768>>>();
    fwd_x_kernel<<<dim3(BT * KM, 2), 768>>>();
    bmlp_kernel<<<BT * NMODE / MPB, 768>>>(w1, b1, w2, b2);
    inv_x_kernel<<<BT * NXD * KM, 768>>>();
    inv_y_kernel<<<BT * NXD, 768>>>(inp);
    ln2_kernel<<<TOK, 256>>>(ln2g, ln2b);
    gemm1_tc_kernel<<<dim3(HID / BN, TOK / BM), 256>>>(mw1, mb1);
    gemm2_tc_kernel<<<dim3(E / BN, TOK / BM), 256>>>(mw2, mb2, out);
}

// round 12
// speedup vs baseline: 3.2883x; 1.3590x over previous
#include <cuda_runtime.h>
#include <cuda_bf16.h>
#include <math.h>
#include <stdint.h>

// Problem constants
#define BT   16          // B*T
#define E    768
#define NXD  32
#define NYD  32
#define NP   1024        // NX*NY
#define TOK  (BT*NP)     // 16384 tokens
#define KM   12          // kept y modes
#define J24  24          // kept x modes (kx = 5..28)
#define KX0  5
#define NMODE 288        // 24*12
#define HID  3072
#define TWO_PI_32 0.19634954084936207f

// ---------------- scratch (static device allocations; no cudaMalloc) ----------------
__device__ float g_h [TOK*E];          // LN1 output
__device__ float g_U [BT*NXD*KM*E];    // fwd y-DFT real
__device__ float g_V [BT*NXD*KM*E];    // fwd y-DFT imag
__device__ float g_fr[BT*NMODE*E];
__device__ float g_fi[BT*NMODE*E];
__device__ float g_sr[BT*NMODE*E];
__device__ float g_si[BT*NMODE*E];
__device__ float g_P [BT*NXD*KM*E];    // inv x-iDFT real (pre-weighted)
__device__ float g_Q [BT*NXD*KM*E];
__device__ float g_r1[TOK*E];          // spat + h + input  (res2)
__device__ float g_y [TOK*E];          // LN2 output
__device__ float g_mid[(size_t)TOK*HID]; // gelu(y@mw1+mb1)

__device__ __forceinline__ float gelu_f(float x) {
    return 0.5f * x * (1.0f + erff(x * 0.7071067811865475f));
}
__device__ __forceinline__ float softshrink_f(float x) {
    return x > 0.01f ? x - 0.01f : (x < -0.01f ? x + 0.01f : 0.0f);
}
__device__ __forceinline__ uint32_t packbf2(float lo, float hi) {
    __nv_bfloat162 p = __floats2bfloat162_rn(lo, hi);   // .x = lo (low 16 bits)
    return *reinterpret_cast<uint32_t*>(&p);
}

// ---------------- LayerNorm (one block per token, 256 threads, 3 elems/thread) ----------------
__device__ __forceinline__ void ln_row(const float* __restrict__ xr,
                                       const float* __restrict__ g,
                                       const float* __restrict__ b,
                                       float* __restrict__ orow) {
    int t = threadIdx.x;
    float v0 = xr[t], v1 = xr[t + 256], v2 = xr[t + 512];
    float s  = v0 + v1 + v2;
    float s2 = v0*v0 + v1*v1 + v2*v2;
    #pragma unroll
    for (int o = 16; o > 0; o >>= 1) {
        s  += __shfl_down_sync(0xffffffffu, s,  o);
        s2 += __shfl_down_sync(0xffffffffu, s2, o);
    }
    __shared__ float sa[8], sb[8];
    __shared__ float mS, rS;
    if ((t & 31) == 0) { sa[t >> 5] = s; sb[t >> 5] = s2; }
    __syncthreads();
    if (t == 0) {
        float ts = 0.f, ts2 = 0.f;
        #pragma unroll
        for (int i = 0; i < 8; i++) { ts += sa[i]; ts2 += sb[i]; }
        float m = ts * (1.0f / 768.0f);
        float var = ts2 * (1.0f / 768.0f) - m * m;
        mS = m; rS = rsqrtf(var + 1e-5f);
    }
    __syncthreads();
    float m = mS, r = rS;
    orow[t]       = (v0 - m) * r * g[t]       + b[t];
    orow[t + 256] = (v1 - m) * r * g[t + 256] + b[t + 256];
    orow[t + 512] = (v2 - m) * r * g[t + 512] + b[t + 512];
}

__global__ void ln1_kernel(const float* __restrict__ x,
                           const float* __restrict__ g,
                           const float* __restrict__ b) {
    size_t row = blockIdx.x;
    ln_row(x + row * E, g, b, g_h + row * E);
}
__global__ void ln2_kernel(const float* __restrict__ g,
                           const float* __restrict__ b) {
    size_t row = blockIdx.x;
    ln_row(g_r1 + row * E, g, b, g_y + row * E);
}

// ---------------- forward DFT stage 1 (over y) ----------------
__global__ void fwd_y_kernel() {
    __shared__ float C[32], S[32];
    if (threadIdx.x < 32) {
        float a = threadIdx.x * TWO_PI_32;
        C[threadIdx.x] = cosf(a); S[threadIdx.x] = sinf(a);
    }
    __syncthreads();
    int e = threadIdx.x;
    int bx = blockIdx.x;                    // bt*32 + x
    float U[KM], V[KM];
    #pragma unroll
    for (int k = 0; k < KM; k++) { U[k] = 0.f; V[k] = 0.f; }
    const float* hp = g_h + (size_t)bx * 32 * E + e;
    for (int y = 0; y < 32; y++) {
        float v = hp[(size_t)y * E];
        #pragma unroll
        for (int ky = 0; ky < KM; ky++) {
            int m = (y * ky) & 31;
            U[ky] += v * C[m];
            V[ky] -= v * S[m];
        }
    }
    float* up = g_U + (size_t)bx * KM * E + e;
    float* vp = g_V + (size_t)bx * KM * E + e;
    #pragma unroll
    for (int ky = 0; ky < KM; ky++) {
        up[(size_t)ky * E] = U[ky];
        vp[(size_t)ky * E] = V[ky];
    }
}

// ---------------- forward DFT stage 2 (over x) ----------------
__global__ void fwd_x_kernel() {
    __shared__ float C[32], S[32];
    if (threadIdx.x < 32) {
        float a = threadIdx.x * TWO_PI_32;
        C[threadIdx.x] = cosf(a); S[threadIdx.x] = sinf(a);
    }
    __syncthreads();
    int e  = threadIdx.x;
    int ky = blockIdx.x % KM;
    int bt = blockIdx.x / KM;
    int j0 = blockIdx.y * 12;
    float fr[12], fi[12];
    #pragma unroll
    for (int j = 0; j < 12; j++) { fr[j] = 0.f; fi[j] = 0.f; }
    const float* up = g_U + ((size_t)(bt * 32) * KM + ky) * E + e;
    const float* vp = g_V + ((size_t)(bt * 32) * KM + ky) * E + e;
    for (int x = 0; x < 32; x++) {
        float u = up[(size_t)x * KM * E];
        float v = vp[(size_t)x * KM * E];
        #pragma unroll
        for (int jj = 0; jj < 12; jj++) {
            int kx = j0 + jj + KX0;
            int m = (kx * x) & 31;
            float c = C[m], s = S[m];
            fr[jj] += u * c + v * s;
            fi[jj] += v * c - u * s;
        }
    }
    const float sc = 1.0f / 32.0f;
    #pragma unroll
    for (int jj = 0; jj < 12; jj++) {
        size_t idx = ((size_t)bt * NMODE + (size_t)(j0 + jj) * KM + ky) * E + e;
        g_fr[idx] = fr[jj] * sc;
        g_fi[idx] = fi[jj] * sc;
    }
}

// ---------------- block-diagonal complex MLP (4 mode-positions per block) ----------------
#define MPB 4
__global__ void bmlp_kernel(const float* __restrict__ w1, const float* __restrict__ b1,
                            const float* __restrict__ w2, const float* __restrict__ b2) {
    __shared__ float sfr[MPB][768], sfi[MPB][768];
    int t = threadIdx.x;
    size_t base = (size_t)blockIdx.x * MPB * E;
    #pragma unroll
    for (int m = 0; m < MPB; m++) {
        sfr[m][t] = g_fr[base + (size_t)m * E + t];
        sfi[m][t] = g_fi[base + (size_t)m * E + t];
    }
    __syncthreads();
    int n = t >> 6;

    const float* w0p = w1 + ((size_t)n * 64) * 64 + (t & 63);
    const float* w1p = w1 + ((size_t)(12 + n) * 64) * 64 + (t & 63);
    float ar[MPB], ai[MPB];
    float bre = b1[t], bim = b1[768 + t];
    #pragma unroll
    for (int m = 0; m < MPB; m++) { ar[m] = bre; ai[m] = bim; }
    #pragma unroll 8
    for (int i = 0; i < 64; i++) {
        float a  = w0p[(size_t)i * 64];
        float bb = w1p[(size_t)i * 64];
        #pragma unroll
        for (int m = 0; m < MPB; m++) {
            float fr = sfr[m][n * 64 + i], fi = sfi[m][n * 64 + i];
            ar[m] += fr * a - fi * bb;
            ai[m] += fi * a + fr * bb;
        }
    }
    __syncthreads();
    #pragma unroll
    for (int m = 0; m < MPB; m++) {
        sfr[m][t] = gelu_f(ar[m]);
        sfi[m][t] = gelu_f(ai[m]);
    }
    __syncthreads();

    const float* u0p = w2 + ((size_t)n * 64) * 64 + (t & 63);
    const float* u1p = w2 + ((size_t)(12 + n) * 64) * 64 + (t & 63);
    float cr[MPB], ci[MPB];
    float cre = b2[t], cim = b2[768 + t];
    #pragma unroll
    for (int m = 0; m < MPB; m++) { cr[m] = cre; ci[m] = cim; }
    #pragma unroll 8
    for (int i = 0; i < 64; i++) {
        float a  = u0p[(size_t)i * 64];
        float bb = u1p[(size_t)i * 64];
        #pragma unroll
        for (int m = 0; m < MPB; m++) {
            float orr = sfr[m][n * 64 + i], oii = sfi[m][n * 64 + i];
            cr[m] += orr * a - oii * bb;
            ci[m] += oii * a + orr * bb;
        }
    }
    #pragma unroll
    for (int m = 0; m < MPB; m++) {
        g_sr[base + (size_t)m * E + t] = softshrink_f(cr[m]);
        g_si[base + (size_t)m * E + t] = softshrink_f(ci[m]);
    }
}

// ---------------- inverse stage 1 (over kx) ----------------
__global__ void inv_x_kernel() {
    __shared__ float C[32], S[32];
    if (threadIdx.x < 32) {
        float a = threadIdx.x * TWO_PI_32;
        C[threadIdx.x] = cosf(a); S[threadIdx.x] = sinf(a);
    }
    __syncthreads();
    int e  = threadIdx.x;
    int bx = blockIdx.x;
    int ky = bx % KM;
    int x  = (bx / KM) % 32;
    int bt = bx / (32 * KM);
    float P = 0.f, Q = 0.f;
    const float* srp = g_sr + ((size_t)bt * NMODE + ky) * E + e;
    const float* sip = g_si + ((size_t)bt * NMODE + ky) * E + e;
    #pragma unroll 4
    for (int j = 0; j < J24; j++) {
        float sr = srp[(size_t)j * KM * E];
        float si = sip[(size_t)j * KM * E];
        int m = ((j + KX0) * x) & 31;
        float c = C[m], s = S[m];
        P += sr * c - si * s;
        Q += sr * s + si * c;
    }
    float wgt = (ky == 0 ? 1.0f : 2.0f) * (1.0f / 32.0f);
    size_t idx = ((size_t)(bt * 32 + x) * KM + ky) * E + e;
    g_P[idx] = P * wgt;
    g_Q[idx] = Q * wgt;
}

// ---------------- inverse stage 2 (over ky) + residual adds ----------------
__global__ void inv_y_kernel(const float* __restrict__ inp) {
    __shared__ float C[32], S[32];
    if (threadIdx.x < 32) {
        float a = threadIdx.x * TWO_PI_32;
        C[threadIdx.x] = cosf(a); S[threadIdx.x] = sinf(a);
    }
    __syncthreads();
    int e = threadIdx.x;
    int bx = blockIdx.x;                   // bt*32 + x
    float P[KM], Q[KM];
    const float* pp = g_P + (size_t)bx * KM * E + e;
    const float* qp = g_Q + (size_t)bx * KM * E + e;
    #pragma unroll
    for (int k = 0; k < KM; k++) {
        P[k] = pp[(size_t)k * E];
        Q[k] = qp[(size_t)k * E];
    }
    for (int y = 0; y < 32; y++) {
        float acc = 0.f;
        #pragma unroll
        for (int ky = 0; ky < KM; ky++) {
            int m = (ky * y) & 31;
            acc += P[ky] * C[m] - Q[ky] * S[m];
        }
        size_t idx = ((size_t)bx * 32 + y) * E + e;
        g_r1[idx] = acc + g_h[idx] + inp[idx];
    }
}

// ======================================================================
//  BF16 tensor-core GEMM, minimal diff from the PROVEN tf32 kernel:
//  identical block/warp tiling (128x128, 8 warps, 64x32 warp tile, BK=16,
//  double buffer), identical fp32 inputs/epilogue. Only change: smem holds
//  packed bf16x2 (converted at the same place to_tf32 sat), fragments are
//  the direct k16 analog of the proven k8 mapping, one m16n8k16 per tile.
// ======================================================================
#define BM 128
#define BN 128
#define BK 16
#define ASP 12      // As word stride per row: 8 words (16 bf16) + 4 pad -> conflict-free
#define BSP 132     // Bp word stride per k-pair row (same 132 structure as proven tf32 B)

__device__ __forceinline__ void mma_bf16(float* c, const uint32_t* a, const uint32_t* b) {
    asm volatile(
        "mma.sync.aligned.m16n8k16.row.col.f32.bf16.bf16.f32 "
        "{%0,%1,%2,%3}, {%4,%5,%6,%7}, {%8,%9}, {%0,%1,%2,%3};\n"
        : "+f"(c[0]), "+f"(c[1]), "+f"(c[2]), "+f"(c[3])
        : "r"(a[0]), "r"(a[1]), "r"(a[2]), "r"(a[3]), "r"(b[0]), "r"(b[1]));
}

template<int N_, bool GELU, bool RESID>
__device__ __forceinline__ void gemm_bf_core(const float* __restrict__ A,
                                             const float* __restrict__ Bm,
                                             const float* __restrict__ bias,
                                             const float* __restrict__ res,
                                             float* __restrict__ Cout, int K) {
    __shared__ uint32_t Asp[2][BM * ASP];   // packed bf16x2 along k
    __shared__ uint32_t Bps[2][8 * BSP];    // [k/2][n] packed {B[2p][n],B[2p+1][n]}

    int t = threadIdx.x;
    int lane = t & 31, wid = t >> 5;
    int gid = lane >> 2, tig = lane & 3;
    int wm = (wid & 1) * 64;            // 2 warps along M
    int wn = (wid >> 1) * 32;           // 4 warps along N
    int m0 = blockIdx.y * BM, n0 = blockIdx.x * BN;

    float acc[4][4][4];
    #pragma unroll
    for (int i = 0; i < 4; i++)
        #pragma unroll
        for (int j = 0; j < 4; j++)
            #pragma unroll
            for (int k = 0; k < 4; k++) acc[i][j][k] = 0.f;

    // global->smem mapping (A: same float4 loads as proven kernel)
    int ar = t >> 2;                    // 0..63 (A rows; +64 for second)
    int ac = (t & 3) * 4;               // k elem offset within tile
    int acw = (t & 3) * 2;              // k word offset (bf16x2)
    // B: each thread packs one k-pair row p over 4 n's
    int bp = t >> 5;                    // 0..7 (k-pair index)
    int bc = (t & 31) * 4;              // n offset
    const float* Ap0 = A + (size_t)(m0 + ar) * K + ac;
    const float* Ap1 = A + (size_t)(m0 + ar + 64) * K + ac;
    const float* Bp0 = Bm + (size_t)(2 * bp) * N_ + n0 + bc;
    const float* Bp1 = Bp0 + N_;

    int NT = K / BK;

    // prologue: tile 0
    {
        float4 a0 = *(const float4*)(Ap0);
        float4 a1 = *(const float4*)(Ap1);
        float4 b0 = *(const float4*)(Bp0);
        float4 b1 = *(const float4*)(Bp1);
        uint32_t* As_ = Asp[0]; uint32_t* Bs_ = Bps[0];
        As_[ar * ASP + acw]            = packbf2(a0.x, a0.y);
        As_[ar * ASP + acw + 1]        = packbf2(a0.z, a0.w);
        As_[(ar + 64) * ASP + acw]     = packbf2(a1.x, a1.y);
        As_[(ar + 64) * ASP + acw + 1] = packbf2(a1.z, a1.w);
        Bs_[bp * BSP + bc + 0] = packbf2(b0.x, b1.x);
        Bs_[bp * BSP + bc + 1] = packbf2(b0.y, b1.y);
        Bs_[bp * BSP + bc + 2] = packbf2(b0.z, b1.z);
        Bs_[bp * BSP + bc + 3] = packbf2(b0.w, b1.w);
    }
    __syncthreads();

    for (int kt = 0; kt < NT; kt++) {
        float4 a0, a1, b0, b1;
        bool has = (kt + 1) < NT;
        if (has) {
            int k0 = (kt + 1) * BK;
            a0 = *(const float4*)(Ap0 + k0);
            a1 = *(const float4*)(Ap1 + k0);
            b0 = *(const float4*)(Bp0 + (size_t)k0 * N_);
            b1 = *(const float4*)(Bp1 + (size_t)k0 * N_);
        }

        const uint32_t* Asb = Asp[kt & 1];
        const uint32_t* Bsb = Bps[kt & 1];
        // fragments: direct k16 analog of the proven k8 mapping
        uint32_t af[4][4];
        #pragma unroll
        for (int ma = 0; ma < 4; ma++) {
            int r = wm + ma * 16 + gid;
            af[ma][0] = Asb[r * ASP + tig];            // {r,   k=2tig..2tig+1}
            af[ma][1] = Asb[(r + 8) * ASP + tig];      // {r+8, k=2tig..2tig+1}
            af[ma][2] = Asb[r * ASP + tig + 4];        // {r,   k=2tig+8..+9}
            af[ma][3] = Asb[(r + 8) * ASP + tig + 4];  // {r+8, k=2tig+8..+9}
        }
        uint32_t bf[4][2];
        #pragma unroll
        for (int na = 0; na < 4; na++) {
            int c = wn + na * 8 + gid;
            bf[na][0] = Bsb[tig * BSP + c];            // {k=2tig..2tig+1,  n=c}
            bf[na][1] = Bsb[(tig + 4) * BSP + c];      // {k=2tig+8..+9,    n=c}
        }
        #pragma unroll
        for (int ma = 0; ma < 4; ma++)
            #pragma unroll
            for (int na = 0; na < 4; na++)
                mma_bf16(acc[ma][na], af[ma], bf[na]);

        if (has) {
            uint32_t* As_ = Asp[(kt + 1) & 1];
            uint32_t* Bs_ = Bps[(kt + 1) & 1];
            As_[ar * ASP + acw]            = packbf2(a0.x, a0.y);
            As_[ar * ASP + acw + 1]        = packbf2(a0.z, a0.w);
            As_[(ar + 64) * ASP + acw]     = packbf2(a1.x, a1.y);
            As_[(ar + 64) * ASP + acw + 1] = packbf2(a1.z, a1.w);
            Bs_[bp * BSP + bc + 0] = packbf2(b0.x, b1.x);
            Bs_[bp * BSP + bc + 1] = packbf2(b0.y, b1.y);
            Bs_[bp * BSP + bc + 2] = packbf2(b0.z, b1.z);
            Bs_[bp * BSP + bc + 3] = packbf2(b0.w, b1.w);
        }
        __syncthreads();
    }

    // epilogue (identical to proven tf32 kernel)
    #pragma unroll
    for (int ma = 0; ma < 4; ma++) {
        size_t r = m0 + wm + ma * 16 + gid;
        #pragma unroll
        for (int na = 0; na < 4; na++) {
            int c = n0 + wn + na * 8 + tig * 2;
            float v0 = acc[ma][na][0] + bias[c];
            float v1 = acc[ma][na][1] + bias[c + 1];
            float v2 = acc[ma][na][2] + bias[c];
            float v3 = acc[ma][na][3] + bias[c + 1];
            if (GELU) { v0 = gelu_f(v0); v1 = gelu_f(v1); v2 = gelu_f(v2); v3 = gelu_f(v3); }
            if (RESID) {
                float2 r0 = *(const float2*)(res + r * N_ + c);
                float2 r1 = *(const float2*)(res + (r + 8) * N_ + c);
                v0 += r0.x; v1 += r0.y; v2 += r1.x; v3 += r1.y;
            }
            *(float2*)(Cout + r * N_ + c) = make_float2(v0, v1);
            *(float2*)(Cout + (r + 8) * N_ + c) = make_float2(v2, v3);
        }
    }
}

__global__ __launch_bounds__(256, 2) void gemm1_bf_kernel(const float* __restrict__ mw1,
                                                          const float* __restrict__ mb1) {
    gemm_bf_core<HID, true, false>(g_y, mw1, mb1, nullptr, g_mid, E);
}
__global__ __launch_bounds__(256, 2) void gemm2_bf_kernel(const float* __restrict__ mw2,
                                                          const float* __restrict__ mb2,
                                                          float* __restrict__ out) {
    gemm_bf_core<E, false, true>(g_mid, mw2, mb2, g_r1, out, HID);
}

// ---------------- launch ----------------
extern "C" void kernel_launch(void* const* d_in, const int* in_sizes, int n_in,
                              void* d_out, int out_size) {
    const float* inp  = (const float*)d_in[0];
    const float* w1   = (const float*)d_in[1];
    const float* b1   = (const float*)d_in[2];
    const float* w2   = (const float*)d_in[3];
    const float* b2   = (const float*)d_in[4];
    const float* ln1g = (const float*)d_in[5];
    const float* ln1b = (const float*)d_in[6];
    const float* ln2g = (const float*)d_in[7];
    const float* ln2b = (const float*)d_in[8];
    const float* mw1  = (const float*)d_in[9];
    const float* mb1  = (const float*)d_in[10];
    const float* mw2  = (const float*)d_in[11];
    const float* mb2  = (const float*)d_in[12];
    float* out = (float*)d_out;

    ln1_kernel<<<TOK, 256>>>(inp, ln1g, ln1b);
    fwd_y_kernel<<<BT * NXD, 768>>>();
    fwd_x_kernel<<<dim3(BT * KM, 2), 768>>>();
    bmlp_kernel<<<BT * NMODE / MPB, 768>>>(w1, b1, w2, b2);
    inv_x_kernel<<<BT * NXD * KM, 768>>>();
    inv_y_kernel<<<BT * NXD, 768>>>(inp);
    ln2_kernel<<<TOK, 256>>>(ln2g, ln2b);
    gemm1_bf_kernel<<<dim3(HID / BN, TOK / BM), 256>>>(mw1, mb1);
    gemm2_bf_kernel<<<dim3(E / BN, TOK / BM), 256>>>(mw2, mb2, out);
}